// round 13
// baseline (speedup 1.0000x reference)
#include <cuda_runtime.h>
#include <stdint.h>
#include <math.h>

#define BB 32
#define NINPUT 1024
#define NN 1024
#define WL 64
#define RR 4
#define IFACE 471
#define OPAD 480
#define KSLICES 8
#define NSTRIPS 16
#define STRIP 64
#define DELTA 1e-6f

typedef unsigned long long u64;

// dynamic smem for k_linkmv: ef 16KB + gh 16KB + tspill 32KB = 64KB
#define LINKMV_SMEM (2*NN*8 + 2*NN*8 + 16*256*8)

// ---------------- scratch (static device memory; no allocation) ----------------
__device__ float g_xi_part[KSLICES][BB][OPAD];
__device__ float g_rk_n[BB*RR*WL];
__device__ float g_rstr[BB*RR];
__device__ float g_erase[BB*WL];
__device__ float g_wv[BB*WL];
__device__ float g_rm[BB*RR*3];
__device__ float g_simw[BB*NN];
__device__ float g_ww[BB*NN];
__device__ float g_Ldiag[BB*NN];
__device__ float g_S1[BB*RR*NN];
__device__ float g_S2[BB*RR*NN];
__device__ float g_Tp[BB][NSTRIPS][8][NN];   // T strip partials (16 MB)
__device__ float g_nm[BB*NN*WL];
__device__ float g_simr[BB*RR*NN];

// ---------------- helpers ----------------
__device__ __forceinline__ float sigmoidf_(float x){ return 1.f/(1.f+expf(-x)); }
__device__ __forceinline__ float softplusf_(float x){ return fmaxf(x,0.f)+log1pf(expf(-fabsf(x))); }

__device__ __forceinline__ u64 pack2(float a, float b){
    u64 r; asm("mov.b64 %0,{%1,%2};":"=l"(r):"f"(a),"f"(b)); return r;
}
__device__ __forceinline__ void unpack2(u64 v, float& a, float& b){
    asm("mov.b64 {%0,%1},%2;":"=f"(a),"=f"(b):"l"(v));
}
__device__ __forceinline__ void fma2(u64& d, u64 a, u64 b){
    asm("fma.rn.f32x2 %0,%1,%2,%0;":"+l"(d):"l"(a),"l"(b));
}
__device__ __forceinline__ u64 add2(u64 a, u64 b){
    u64 r; asm("add.rn.f32x2 %0,%1,%2;":"=l"(r):"l"(a),"l"(b)); return r;
}

// ================= K1: interface GEMM (tiled, k-sliced partials) =================
__global__ void __launch_bounds__(256) k_gemm(const float* __restrict__ x,
                                              const float* __restrict__ W){
    int otile = blockIdx.x, ks = blockIdx.y;
    int t = threadIdx.x;
    __shared__ float ws[128][32];
    __shared__ float xs[32][128];
    int o0 = otile*32, k0 = ks*128;
    {
        int oo = t & 31, r0 = t >> 5;
        int o = o0 + oo;
        for (int r = r0; r < 128; r += 8)
            ws[r][oo] = (o < IFACE) ? W[(size_t)(k0 + r)*IFACE + o] : 0.f;
    }
    {
        int kk = t & 127, b0 = t >> 7;
        for (int b = b0; b < 32; b += 2)
            xs[b][kk] = x[b*NINPUT + k0 + kk];
    }
    __syncthreads();
    int p = t & 15;
    int b0 = (t >> 4)*2;
    u64 a0 = 0ull, a1 = 0ull;
    #pragma unroll 8
    for (int kk = 0; kk < 128; kk++){
        u64 wp = *reinterpret_cast<const u64*>(&ws[kk][p*2]);
        float xb0 = xs[b0][kk], xb1 = xs[b0+1][kk];
        fma2(a0, wp, pack2(xb0,xb0));
        fma2(a1, wp, pack2(xb1,xb1));
    }
    float f0,f1;
    unpack2(a0,f0,f1);
    g_xi_part[ks][b0  ][o0+p*2]=f0; g_xi_part[ks][b0  ][o0+p*2+1]=f1;
    unpack2(a1,f0,f1);
    g_xi_part[ks][b0+1][o0+p*2]=f0; g_xi_part[ks][b0+1][o0+p*2+1]=f1;
}

// ================= K2: write content similarity (staged transpose, coalesced) ====
__global__ void __launch_bounds__(128) k_simw(const float* __restrict__ mem,
                                              const float* __restrict__ bias){
    int b = blockIdx.x;
    int t = threadIdx.x;
    int row0 = blockIdx.y*128;
    __shared__ float tile[128][65];
    __shared__ float wk[64];
    __shared__ float invwk;
    if (t < 64){
        float acc = bias[260+t];
        #pragma unroll
        for (int ks=0; ks<KSLICES; ks++) acc += g_xi_part[ks][b][260+t];
        wk[t] = tanhf(acc);
    }
    __syncthreads();
    if (t < 32){
        float s = wk[t]*wk[t] + wk[t+32]*wk[t+32];
        #pragma unroll
        for (int m=16;m;m>>=1) s += __shfl_xor_sync(0xffffffffu, s, m);
        if (t==0) invwk = 1.f/(sqrtf(s)+DELTA);
    }
    const float2* m2 = reinterpret_cast<const float2*>(mem);
    #pragma unroll
    for (int idx=t; idx<128*32; idx+=128){
        int row = idx>>5, c2 = idx&31;
        float2 v = m2[((size_t)b*NN + row0+row)*32 + c2];
        tile[row][c2*2]=v.x; tile[row][c2*2+1]=v.y;
    }
    __syncthreads();
    int n = row0 + t;
    float nsq=0.f, dot=0.f;
    #pragma unroll
    for (int w=0;w<64;w++){
        float v = tile[t][w];
        nsq += v*v;
        dot += v*wk[w];
    }
    g_simw[b*NN+n] = dot / (sqrtf(nsq)+DELTA) * invwk;
}

// ================= K3: act + usage + bitonic argsort + scan + ww ==============
__device__ __forceinline__ bool lexless(float va, int ia, float vb, int ib){
    return (va < vb) || (va == vb && ia < ib);
}

__global__ void __launch_bounds__(1024) k_alloc(const float* __restrict__ bias,
                        const float* __restrict__ usage, const float* __restrict__ wwold,
                        const float* __restrict__ rw, const float* __restrict__ link){
    int b = blockIdx.x; int t = threadIdx.x; // 1024 threads
    __shared__ float act[IFACE+1];
    __shared__ float norms[4];
    __shared__ float sv[NN];
    __shared__ int   si[NN];
    __shared__ float tbuf[NN];
    __shared__ float red[32];
    __shared__ float wp[32], wscan[32];

    // ---- stage A: activations ----
    if (t < IFACE){
        float acc = bias[t];
        #pragma unroll
        for (int ks=0; ks<KSLICES; ks++) acc += g_xi_part[ks][b][t];
        float v;
        if (t < 256)       v = tanhf(acc);
        else if (t < 260)  v = softplusf_(acc);
        else if (t < 324)  v = tanhf(acc);
        else if (t == 324) v = softplusf_(acc);
        else if (t < 389)  v = sigmoidf_(acc);
        else if (t < 453)  v = tanhf(acc);
        else if (t < 459)  v = sigmoidf_(acc);
        else               v = acc;
        act[t] = v;
    }
    __syncthreads();
    if (t < 128){
        int g = t>>5, l = t&31;
        const float* base = act + g*64;
        float s = base[l]*base[l] + base[l+32]*base[l+32];
        #pragma unroll
        for (int m=16;m;m>>=1) s += __shfl_xor_sync(0xffffffffu, s, m);
        if (l==0) norms[g] = sqrtf(s) + DELTA;
    }
    __syncthreads();
    if (t < 256)       g_rk_n[b*256+t] = act[t] / norms[t>>6];
    else if (t < 260)  g_rstr[b*4 + (t-256)] = act[t];
    else if (t >= 325 && t < 389)  g_erase[b*64 + (t-325)] = act[t];
    else if (t >= 389 && t < 453)  g_wv[b*64 + (t-389)] = act[t];
    if (t < 4){
        float a0=act[459+t*3], a1=act[460+t*3], a2=act[461+t*3];
        float mx=fmaxf(a0,fmaxf(a1,a2));
        float e0=expf(a0-mx), e1=expf(a1-mx), e2=expf(a2-mx);
        float inv=1.f/(e0+e1+e2);
        g_rm[b*12+t*3+0]=e0*inv; g_rm[b*12+t*3+1]=e1*inv; g_rm[b*12+t*3+2]=e2*inv;
    }

    // ---- stage B: usage ----
    float us = usage[b*NN+t];
    float u = us + (1.f-us)*wwold[b*NN+t];
    float psi = 1.f;
    #pragma unroll
    for (int r=0;r<4;r++) psi *= (1.f - act[453+r]*rw[(b*4+r)*NN+t]);
    u *= psi;
    u = DELTA + (1.f-DELTA)*u;

    // ---- stage C: bitonic argsort on (value, index), shfl for j<=16 ----
    float v = u; int idx = t;
    for (int k=2;k<=NN;k<<=1){
        bool up = ((t & k)==0);
        for (int j=k>>1;j>0;j>>=1){
            float pv; int pidx;
            if (j >= 32){
                sv[t]=v; si[t]=idx;
                __syncthreads();
                pv = sv[t^j]; pidx = si[t^j];
                __syncthreads();
            } else {
                pv   = __shfl_xor_sync(0xffffffffu, v, j);
                pidx = __shfl_xor_sync(0xffffffffu, idx, j);
            }
            bool iAmLow = ((t & j) == 0);
            bool mineLess = lexless(v, idx, pv, pidx);
            bool takePartner = (mineLess != (iAmLow == up));
            if (takePartner){ v = pv; idx = pidx; }
        }
    }

    // ---- stage D: multiplicative exclusive scan of sorted values ----
    {
        int lane = t & 31, warp = t >> 5;
        float p = v;
        #pragma unroll
        for (int d=1; d<32; d<<=1){
            float q = __shfl_up_sync(0xffffffffu, p, d);
            if (lane >= d) p *= q;
        }
        if (lane==31) wp[warp] = p;
        __syncthreads();
        if (t < 32){
            float q = wp[t];
            #pragma unroll
            for (int d=1; d<32; d<<=1){
                float z = __shfl_up_sync(0xffffffffu, q, d);
                if (t >= d) q *= z;
            }
            wscan[t] = q;
        }
        __syncthreads();
        float prefix = (warp==0)? 1.f : wscan[warp-1];
        float exw = __shfl_up_sync(0xffffffffu, p, 1);
        if (lane==0) exw = 1.f;
        float excl = exw * prefix;
        tbuf[idx] = (1.f - v) * excl;   // scatter to original order
    }
    __syncthreads();

    // ---- stage E: write-content softmax + ww ----
    float beta = act[324];
    float s = g_simw[b*NN+t]*beta;
    float m = s;
    #pragma unroll
    for (int mm=16;mm;mm>>=1) m = fmaxf(m, __shfl_xor_sync(0xffffffffu,m,mm));
    if ((t&31)==0) red[t>>5]=m;
    __syncthreads();
    if (t==0){ float z=red[0]; for (int i=1;i<32;i++) z=fmaxf(z,red[i]); red[0]=z; }
    __syncthreads();
    m = red[0];
    float e = expf(s-m);
    float ssum = e;
    #pragma unroll
    for (int mm=16;mm;mm>>=1) ssum += __shfl_xor_sync(0xffffffffu,ssum,mm);
    __syncthreads();
    if ((t&31)==0) red[t>>5]=ssum;
    __syncthreads();
    if (t==0){ float z=0.f; for (int i=0;i<32;i++) z+=red[i]; red[0]=z; }
    __syncthreads();
    float wcw = e/red[0];
    float ag = act[457], wg = act[458];
    g_ww[b*NN+t] = wg*(ag*tbuf[t] + (1.f-ag)*wcw);
    g_Ldiag[b*NN+t] = link[((size_t)b*NN + t)*NN + t];
}

// ================= K4: chunk-interleaved link matvecs, T-acc smem spill =========
// grid (BB, 16), 3 blocks/SM (64KB dyn smem, regs<=85). Phase T streams from DRAM
// (reg accumulators, spilled to smem at chunk end); phase S re-reads same 128KB
// from L2 with full register freedom. Interleaved coef arrays -> LDS.128.
__global__ void __launch_bounds__(256, 3) k_linkmv(const float* __restrict__ link,
                                                   const float* __restrict__ rw){
    extern __shared__ __align__(16) u64 dyn[];
    u64* ef  = dyn;            // [n*2+0]=e01(rw0,rw1), [n*2+1]=e23(rw2,rw3)
    u64* gh  = dyn + 2*NN;     // [n*2+0]=f01, [n*2+1]=f23
    u64* tsp = dyn + 4*NN;     // [k*256 + t], k<16

    int b = blockIdx.x, s = blockIdx.y;
    int t = threadIdx.x;
    for (int n=t;n<NN;n+=256){
        float r0=rw[(b*4+0)*NN+n], r1=rw[(b*4+1)*NN+n];
        float r2=rw[(b*4+2)*NN+n], r3=rw[(b*4+3)*NN+n];
        float w = g_ww[b*NN+n];
        ef[n*2]=pack2(r0,r1); ef[n*2+1]=pack2(r2,r3);
        gh[n*2]=pack2(r0*w,r1*w); gh[n*2+1]=pack2(r2*w,r3*w);
    }
    __syncthreads();
    const float* Lb = link + (size_t)b*NN*NN;
    int i0 = s*STRIP;
    int wid = t>>5, lane = t&31;

    #pragma unroll
    for (int ch=0; ch<2; ch++){
        int c0 = i0 + ch*32;
        // ---- phase T: stream 32 rows (128KB) from DRAM ----
        {
            u64 T1a[4], T1b[4], T2a[4], T2b[4];
            if (ch==0){
                #pragma unroll
                for (int c=0;c<4;c++){ T1a[c]=0ull; T1b[c]=0ull; T2a[c]=0ull; T2b[c]=0ull; }
            } else {
                #pragma unroll
                for (int c=0;c<4;c++){
                    T1a[c]=tsp[c*256+t]; T1b[c]=tsp[(4+c)*256+t];
                    T2a[c]=tsp[(8+c)*256+t]; T2b[c]=tsp[(12+c)*256+t];
                }
            }
            #pragma unroll 2
            for (int i=0;i<32;i+=4){
                float4 lv[4];
                #pragma unroll
                for (int k=0;k<4;k++)
                    lv[k] = reinterpret_cast<const float4*>(Lb + (size_t)(c0+i+k)*NN)[t];
                #pragma unroll
                for (int k=0;k<4;k++){
                    int row = c0+i+k;
                    ulonglong2 ce = *reinterpret_cast<const ulonglong2*>(&ef[row*2]);
                    ulonglong2 cf = *reinterpret_cast<const ulonglong2*>(&gh[row*2]);
                    float l[4] = {lv[k].x, lv[k].y, lv[k].z, lv[k].w};
                    #pragma unroll
                    for (int c=0;c<4;c++){
                        u64 p = pack2(l[c], l[c]);
                        fma2(T1a[c],p,ce.x); fma2(T1b[c],p,ce.y);
                        fma2(T2a[c],p,cf.x); fma2(T2b[c],p,cf.y);
                    }
                }
            }
            // spill T accumulators to smem (registers die here)
            #pragma unroll
            for (int c=0;c<4;c++){
                tsp[c*256+t]=T1a[c]; tsp[(4+c)*256+t]=T1b[c];
                tsp[(8+c)*256+t]=T2a[c]; tsp[(12+c)*256+t]=T2b[c];
            }
        }
        __syncthreads();
        // ---- phase S: rows of this chunk, reading L2-hot lines ----
        {
            int r0i = c0 + wid*4;
            u64 acc[4][4];
            #pragma unroll
            for (int a=0;a<4;a++)
                #pragma unroll
                for (int c=0;c<4;c++) acc[a][c]=0ull;
            const float* L0 = Lb + (size_t)r0i*NN + lane;
            #pragma unroll 4
            for (int it=0; it<32; it++){
                int j = it*32 + lane;
                float lv0=L0[it*32];
                float lv1=L0[it*32+NN];
                float lv2=L0[it*32+2*NN];
                float lv3=L0[it*32+3*NN];
                ulonglong2 eab = *reinterpret_cast<const ulonglong2*>(&ef[j*2]);
                ulonglong2 fab = *reinterpret_cast<const ulonglong2*>(&gh[j*2]);
                u64 p0=pack2(lv0,lv0), p1=pack2(lv1,lv1), p2=pack2(lv2,lv2), p3=pack2(lv3,lv3);
                fma2(acc[0][0],p0,eab.x); fma2(acc[0][1],p0,eab.y); fma2(acc[0][2],p0,fab.x); fma2(acc[0][3],p0,fab.y);
                fma2(acc[1][0],p1,eab.x); fma2(acc[1][1],p1,eab.y); fma2(acc[1][2],p1,fab.x); fma2(acc[1][3],p1,fab.y);
                fma2(acc[2][0],p2,eab.x); fma2(acc[2][1],p2,eab.y); fma2(acc[2][2],p2,fab.x); fma2(acc[2][3],p2,fab.y);
                fma2(acc[3][0],p3,eab.x); fma2(acc[3][1],p3,eab.y); fma2(acc[3][2],p3,fab.x); fma2(acc[3][3],p3,fab.y);
            }
            #pragma unroll
            for (int row=0;row<4;row++)
                #pragma unroll
                for (int c=0;c<4;c++)
                    #pragma unroll
                    for (int m=16;m;m>>=1)
                        acc[row][c] = add2(acc[row][c], __shfl_xor_sync(0xffffffffu, acc[row][c], m));
            if (lane==0){
                #pragma unroll
                for (int row=0;row<4;row++){
                    int i = r0i+row;
                    float lo,hi;
                    unpack2(acc[row][0],lo,hi); g_S1[(b*4+0)*NN+i]=lo; g_S1[(b*4+1)*NN+i]=hi;
                    unpack2(acc[row][1],lo,hi); g_S1[(b*4+2)*NN+i]=lo; g_S1[(b*4+3)*NN+i]=hi;
                    unpack2(acc[row][2],lo,hi); g_S2[(b*4+0)*NN+i]=lo; g_S2[(b*4+1)*NN+i]=hi;
                    unpack2(acc[row][3],lo,hi); g_S2[(b*4+2)*NN+i]=lo; g_S2[(b*4+3)*NN+i]=hi;
                }
            }
        }
        __syncthreads();   // protect tsp before next chunk reload
    }

    // ---- write T strip partials (float4 coalesced) from smem spill ----
    {
        float lo[4], hi[4];
        float4* tp;
        u64 v[4];
        #pragma unroll
        for (int c=0;c<4;c++){ v[c]=tsp[c*256+t]; unpack2(v[c], lo[c], hi[c]); }
        tp = reinterpret_cast<float4*>(&g_Tp[b][s][0][0]); tp[t] = make_float4(lo[0],lo[1],lo[2],lo[3]);
        tp = reinterpret_cast<float4*>(&g_Tp[b][s][1][0]); tp[t] = make_float4(hi[0],hi[1],hi[2],hi[3]);
        #pragma unroll
        for (int c=0;c<4;c++){ v[c]=tsp[(4+c)*256+t]; unpack2(v[c], lo[c], hi[c]); }
        tp = reinterpret_cast<float4*>(&g_Tp[b][s][2][0]); tp[t] = make_float4(lo[0],lo[1],lo[2],lo[3]);
        tp = reinterpret_cast<float4*>(&g_Tp[b][s][3][0]); tp[t] = make_float4(hi[0],hi[1],hi[2],hi[3]);
        #pragma unroll
        for (int c=0;c<4;c++){ v[c]=tsp[(8+c)*256+t]; unpack2(v[c], lo[c], hi[c]); }
        tp = reinterpret_cast<float4*>(&g_Tp[b][s][4][0]); tp[t] = make_float4(lo[0],lo[1],lo[2],lo[3]);
        tp = reinterpret_cast<float4*>(&g_Tp[b][s][5][0]); tp[t] = make_float4(hi[0],hi[1],hi[2],hi[3]);
        #pragma unroll
        for (int c=0;c<4;c++){ v[c]=tsp[(12+c)*256+t]; unpack2(v[c], lo[c], hi[c]); }
        tp = reinterpret_cast<float4*>(&g_Tp[b][s][6][0]); tp[t] = make_float4(lo[0],lo[1],lo[2],lo[3]);
        tp = reinterpret_cast<float4*>(&g_Tp[b][s][7][0]); tp[t] = make_float4(hi[0],hi[1],hi[2],hi[3]);
    }
}

// ================= K5: new memory + read content sims (staged transpose) ========
__global__ void __launch_bounds__(128) k_newmem(const float* __restrict__ mem){
    int b = blockIdx.x;
    int t = threadIdx.x;
    int row0 = blockIdx.y*128;
    __shared__ float tile[128][65];
    __shared__ float er[64], wv[64], rk[256];
    if (t<64){ er[t]=g_erase[b*64+t]; wv[t]=g_wv[b*64+t]; }
    for (int i=t;i<256;i+=128) rk[i]=g_rk_n[b*256+i];
    const float2* m2 = reinterpret_cast<const float2*>(mem);
    #pragma unroll
    for (int idx=t; idx<128*32; idx+=128){
        int row = idx>>5, c2 = idx&31;
        float2 v = m2[((size_t)b*NN + row0+row)*32 + c2];
        tile[row][c2*2]=v.x; tile[row][c2*2+1]=v.y;
    }
    __syncthreads();
    int n = row0 + t;
    float wwn = g_ww[b*NN+n];
    float nsq=0.f, d0=0.f, d1=0.f, d2=0.f, d3=0.f;
    #pragma unroll
    for (int w=0;w<64;w++){
        float nv = tile[t][w]*(1.f - wwn*er[w]) + wwn*wv[w];
        tile[t][w] = nv;
        nsq += nv*nv;
        d0  += nv*rk[0*64+w];
        d1  += nv*rk[1*64+w];
        d2  += nv*rk[2*64+w];
        d3  += nv*rk[3*64+w];
    }
    float inv = 1.f/(sqrtf(nsq)+DELTA);
    g_simr[(b*4+0)*NN+n]=d0*inv;
    g_simr[(b*4+1)*NN+n]=d1*inv;
    g_simr[(b*4+2)*NN+n]=d2*inv;
    g_simr[(b*4+3)*NN+n]=d3*inv;
    __syncthreads();
    float2* o2 = reinterpret_cast<float2*>(g_nm);
    #pragma unroll
    for (int idx=t; idx<128*32; idx+=128){
        int row = idx>>5, c2 = idx&31;
        o2[((size_t)b*NN + row0+row)*32 + c2] = make_float2(tile[row][c2*2], tile[row][c2*2+1]);
    }
}

// ================= K6: assembly + output (R4 proven) ==========================
__device__ __forceinline__ float blockSum512(float v, float* red){
    int t=threadIdx.x;
    #pragma unroll
    for (int m=16;m;m>>=1) v += __shfl_xor_sync(0xffffffffu,v,m);
    __syncthreads();
    if ((t&31)==0) red[t>>5]=v;
    __syncthreads();
    if (t==0){ float z=0.f; for (int i=0;i<16;i++) z+=red[i]; red[0]=z; }
    __syncthreads();
    float r = red[0];
    __syncthreads();
    return r;
}
__device__ __forceinline__ float blockMax512(float v, float* red){
    int t=threadIdx.x;
    #pragma unroll
    for (int m=16;m;m>>=1) v = fmaxf(v, __shfl_xor_sync(0xffffffffu,v,m));
    __syncthreads();
    if ((t&31)==0) red[t>>5]=v;
    __syncthreads();
    if (t==0){ float z=red[0]; for (int i=1;i<16;i++) z=fmaxf(z,red[i]); red[0]=z; }
    __syncthreads();
    float r = red[0];
    __syncthreads();
    return r;
}

__global__ void __launch_bounds__(512) k_read(const float* __restrict__ prec,
                                              const float* __restrict__ rw,
                                              float* __restrict__ out){
    int b = blockIdx.x, r = blockIdx.y;
    int t = threadIdx.x;
    int br = b*4+r;
    __shared__ float nrw[NN];
    __shared__ float pout[512];
    __shared__ float red[16];
    float s1[2],s2[2],t1[2],t2[2],wwv[2],pv[2],rv[2],ldv[2],sv[2];
    float beta = g_rstr[br];
    float dpart=0.f, epart=0.f, mpart=-1e30f;
    #pragma unroll
    for (int k=0;k<2;k++){
        int n = t + k*512;
        s1[k]=g_S1[br*NN+n]; s2[k]=g_S2[br*NN+n];
        float a1=0.f, a2=0.f;
        #pragma unroll 8
        for (int st=0; st<NSTRIPS; st++){
            a1 += g_Tp[b][st][r][n];
            a2 += g_Tp[b][st][4+r][n];
        }
        t1[k]=a1; t2[k]=a2;
        wwv[k]=g_ww[b*NN+n]; pv[k]=prec[b*NN+n];
        rv[k]=rw[br*NN+n];   ldv[k]=g_Ldiag[b*NN+n];
        sv[k]=g_simr[br*NN+n]*beta;
        dpart += pv[k]*rv[k];
        epart += wwv[k]*rv[k];
        mpart = fmaxf(mpart, sv[k]);
    }
    float D = blockSum512(dpart, red);
    float E = blockSum512(epart, red);
    float M = blockMax512(mpart, red);
    float ex[2]; float spart=0.f;
    #pragma unroll
    for (int k=0;k<2;k++){ ex[k]=expf(sv[k]-M); spart+=ex[k]; }
    float S = blockSum512(spart, red);
    float invS = 1.f/S;
    float rm0=g_rm[b*12+r*3+0], rm1=g_rm[b*12+r*3+1], rm2=g_rm[b*12+r*3+2];
    #pragma unroll
    for (int k=0;k<2;k++){
        int n = t + k*512;
        float w = wwv[k];
        float diag = ((1.f-2.f*w)*ldv[k] + w*pv[k])*rv[k];
        float fwd = (1.f-w)*s1[k] - s2[k] + w*D - diag;
        float bwd = (1.f-w)*t1[k] - t2[k] + pv[k]*E - diag;
        float crw = ex[k]*invS;
        nrw[n] = rm0*bwd + rm1*crw + rm2*fwd;
    }
    __syncthreads();
    int w = t & 63, chunk = t >> 6;
    const float* nm = g_nm + (size_t)b*NN*WL;
    float a0=0.f,a1=0.f,a2=0.f,a3=0.f;
    int n0 = chunk*128;
    for (int n=n0; n<n0+128; n+=4){
        a0 = fmaf(nrw[n  ], nm[(size_t)(n  )*WL + w], a0);
        a1 = fmaf(nrw[n+1], nm[(size_t)(n+1)*WL + w], a1);
        a2 = fmaf(nrw[n+2], nm[(size_t)(n+2)*WL + w], a2);
        a3 = fmaf(nrw[n+3], nm[(size_t)(n+3)*WL + w], a3);
    }
    pout[t] = (a0+a1)+(a2+a3);
    __syncthreads();
    if (t < 64){
        float s = 0.f;
        #pragma unroll
        for (int c=0;c<8;c++) s += pout[c*64+t];
        out[br*64+t] = s;
    }
}

// ================= launch =================
extern "C" void kernel_launch(void* const* d_in, const int* in_sizes, int n_in,
                              void* d_out, int out_size){
    const float* x     = (const float*)d_in[0];
    const float* W     = (const float*)d_in[1];
    const float* bias  = (const float*)d_in[2];
    const float* mem   = (const float*)d_in[3];
    const float* link  = (const float*)d_in[4];
    const float* prec  = (const float*)d_in[5];
    const float* rw    = (const float*)d_in[6];
    const float* wwold = (const float*)d_in[7];
    const float* usage = (const float*)d_in[8];
    float* out = (float*)d_out;

    cudaFuncSetAttribute(k_linkmv, cudaFuncAttributeMaxDynamicSharedMemorySize, LINKMV_SMEM);

    k_gemm<<<dim3(15, KSLICES), 256>>>(x, W);
    k_simw<<<dim3(BB, 8), 128>>>(mem, bias);
    k_alloc<<<BB, 1024>>>(bias, usage, wwold, rw, link);
    k_linkmv<<<dim3(BB, NSTRIPS), 256, LINKMV_SMEM>>>(link, rw);
    k_newmem<<<dim3(BB, 8), 128>>>(mem);
    k_read<<<dim3(BB,RR), 512>>>(prec, rw, out);
}

// round 15
// speedup vs baseline: 1.0023x; 1.0023x over previous
#include <cuda_runtime.h>
#include <stdint.h>
#include <math.h>

#define BB 32
#define NINPUT 1024
#define NN 1024
#define WL 64
#define RR 4
#define IFACE 471
#define OPAD 480
#define KSLICES 8
#define NSTRIPS 16
#define STRIP 64
#define DELTA 1e-6f

typedef unsigned long long u64;

// ---------------- scratch (static device memory; no allocation) ----------------
__device__ float g_xi_part[KSLICES][BB][OPAD];
__device__ float g_rk_n[BB*RR*WL];
__device__ float g_rstr[BB*RR];
__device__ float g_erase[BB*WL];
__device__ float g_wv[BB*WL];
__device__ float g_rm[BB*RR*3];
__device__ float g_simw[BB*NN];
__device__ float g_ww[BB*NN];
__device__ float g_Ldiag[BB*NN];
__device__ float g_S1[BB*RR*NN];
__device__ float g_S2[BB*RR*NN];
__device__ float g_Tp[BB][NSTRIPS][8][NN];   // T strip partials (16 MB)
__device__ float g_nm[BB*NN*WL];
__device__ float g_simr[BB*RR*NN];

// ---------------- helpers ----------------
__device__ __forceinline__ float sigmoidf_(float x){ return 1.f/(1.f+expf(-x)); }
__device__ __forceinline__ float softplusf_(float x){ return fmaxf(x,0.f)+log1pf(expf(-fabsf(x))); }

__device__ __forceinline__ u64 pack2(float a, float b){
    u64 r; asm("mov.b64 %0,{%1,%2};":"=l"(r):"f"(a),"f"(b)); return r;
}
__device__ __forceinline__ void unpack2(u64 v, float& a, float& b){
    asm("mov.b64 {%0,%1},%2;":"=f"(a),"=f"(b):"l"(v));
}
__device__ __forceinline__ void fma2(u64& d, u64 a, u64 b){
    asm("fma.rn.f32x2 %0,%1,%2,%0;":"+l"(d):"l"(a),"l"(b));
}
__device__ __forceinline__ u64 add2(u64 a, u64 b){
    u64 r; asm("add.rn.f32x2 %0,%1,%2;":"=l"(r):"l"(a),"l"(b)); return r;
}

// ================= K1: interface GEMM (tiled, k-sliced partials) =================
__global__ void __launch_bounds__(256) k_gemm(const float* __restrict__ x,
                                              const float* __restrict__ W){
    int otile = blockIdx.x, ks = blockIdx.y;
    int t = threadIdx.x;
    __shared__ float ws[128][32];
    __shared__ float xs[32][128];
    int o0 = otile*32, k0 = ks*128;
    {
        int oo = t & 31, r0 = t >> 5;
        int o = o0 + oo;
        for (int r = r0; r < 128; r += 8)
            ws[r][oo] = (o < IFACE) ? W[(size_t)(k0 + r)*IFACE + o] : 0.f;
    }
    {
        int kk = t & 127, b0 = t >> 7;
        for (int b = b0; b < 32; b += 2)
            xs[b][kk] = x[b*NINPUT + k0 + kk];
    }
    __syncthreads();
    int p = t & 15;
    int b0 = (t >> 4)*2;
    u64 a0 = 0ull, a1 = 0ull;
    #pragma unroll 8
    for (int kk = 0; kk < 128; kk++){
        u64 wp = *reinterpret_cast<const u64*>(&ws[kk][p*2]);
        float xb0 = xs[b0][kk], xb1 = xs[b0+1][kk];
        fma2(a0, wp, pack2(xb0,xb0));
        fma2(a1, wp, pack2(xb1,xb1));
    }
    float f0,f1;
    unpack2(a0,f0,f1);
    g_xi_part[ks][b0  ][o0+p*2]=f0; g_xi_part[ks][b0  ][o0+p*2+1]=f1;
    unpack2(a1,f0,f1);
    g_xi_part[ks][b0+1][o0+p*2]=f0; g_xi_part[ks][b0+1][o0+p*2+1]=f1;
}

// ================= K2: write content similarity (staged transpose, coalesced) ====
__global__ void __launch_bounds__(128) k_simw(const float* __restrict__ mem,
                                              const float* __restrict__ bias){
    int b = blockIdx.x;
    int t = threadIdx.x;
    int row0 = blockIdx.y*128;
    __shared__ float tile[128][65];
    __shared__ float wk[64];
    __shared__ float invwk;
    if (t < 64){
        float acc = bias[260+t];
        #pragma unroll
        for (int ks=0; ks<KSLICES; ks++) acc += g_xi_part[ks][b][260+t];
        wk[t] = tanhf(acc);
    }
    __syncthreads();
    if (t < 32){
        float s = wk[t]*wk[t] + wk[t+32]*wk[t+32];
        #pragma unroll
        for (int m=16;m;m>>=1) s += __shfl_xor_sync(0xffffffffu, s, m);
        if (t==0) invwk = 1.f/(sqrtf(s)+DELTA);
    }
    const float2* m2 = reinterpret_cast<const float2*>(mem);
    #pragma unroll
    for (int idx=t; idx<128*32; idx+=128){
        int row = idx>>5, c2 = idx&31;
        float2 v = m2[((size_t)b*NN + row0+row)*32 + c2];
        tile[row][c2*2]=v.x; tile[row][c2*2+1]=v.y;
    }
    __syncthreads();
    int n = row0 + t;
    float nsq=0.f, dot=0.f;
    #pragma unroll
    for (int w=0;w<64;w++){
        float v = tile[t][w];
        nsq += v*v;
        dot += v*wk[w];
    }
    g_simw[b*NN+n] = dot / (sqrtf(nsq)+DELTA) * invwk;
}

// ================= K3: act + usage + bitonic argsort + scan + ww ==============
__device__ __forceinline__ bool lexless(float va, int ia, float vb, int ib){
    return (va < vb) || (va == vb && ia < ib);
}

__global__ void __launch_bounds__(1024) k_alloc(const float* __restrict__ bias,
                        const float* __restrict__ usage, const float* __restrict__ wwold,
                        const float* __restrict__ rw, const float* __restrict__ link){
    int b = blockIdx.x; int t = threadIdx.x; // 1024 threads
    __shared__ float act[IFACE+1];
    __shared__ float norms[4];
    __shared__ float sv[NN];
    __shared__ int   si[NN];
    __shared__ float tbuf[NN];
    __shared__ float red[32];
    __shared__ float wp[32], wscan[32];

    // ---- stage A: activations ----
    if (t < IFACE){
        float acc = bias[t];
        #pragma unroll
        for (int ks=0; ks<KSLICES; ks++) acc += g_xi_part[ks][b][t];
        float v;
        if (t < 256)       v = tanhf(acc);
        else if (t < 260)  v = softplusf_(acc);
        else if (t < 324)  v = tanhf(acc);
        else if (t == 324) v = softplusf_(acc);
        else if (t < 389)  v = sigmoidf_(acc);
        else if (t < 453)  v = tanhf(acc);
        else if (t < 459)  v = sigmoidf_(acc);
        else               v = acc;
        act[t] = v;
    }
    __syncthreads();
    if (t < 128){
        int g = t>>5, l = t&31;
        const float* base = act + g*64;
        float s = base[l]*base[l] + base[l+32]*base[l+32];
        #pragma unroll
        for (int m=16;m;m>>=1) s += __shfl_xor_sync(0xffffffffu, s, m);
        if (l==0) norms[g] = sqrtf(s) + DELTA;
    }
    __syncthreads();
    if (t < 256)       g_rk_n[b*256+t] = act[t] / norms[t>>6];
    else if (t < 260)  g_rstr[b*4 + (t-256)] = act[t];
    else if (t >= 325 && t < 389)  g_erase[b*64 + (t-325)] = act[t];
    else if (t >= 389 && t < 453)  g_wv[b*64 + (t-389)] = act[t];
    if (t < 4){
        float a0=act[459+t*3], a1=act[460+t*3], a2=act[461+t*3];
        float mx=fmaxf(a0,fmaxf(a1,a2));
        float e0=expf(a0-mx), e1=expf(a1-mx), e2=expf(a2-mx);
        float inv=1.f/(e0+e1+e2);
        g_rm[b*12+t*3+0]=e0*inv; g_rm[b*12+t*3+1]=e1*inv; g_rm[b*12+t*3+2]=e2*inv;
    }

    // ---- stage B: usage ----
    float us = usage[b*NN+t];
    float u = us + (1.f-us)*wwold[b*NN+t];
    float psi = 1.f;
    #pragma unroll
    for (int r=0;r<4;r++) psi *= (1.f - act[453+r]*rw[(b*4+r)*NN+t]);
    u *= psi;
    u = DELTA + (1.f-DELTA)*u;

    // ---- stage C: bitonic argsort on (value, index), shfl for j<=16 ----
    float v = u; int idx = t;
    for (int k=2;k<=NN;k<<=1){
        bool up = ((t & k)==0);
        for (int j=k>>1;j>0;j>>=1){
            float pv; int pidx;
            if (j >= 32){
                sv[t]=v; si[t]=idx;
                __syncthreads();
                pv = sv[t^j]; pidx = si[t^j];
                __syncthreads();
            } else {
                pv   = __shfl_xor_sync(0xffffffffu, v, j);
                pidx = __shfl_xor_sync(0xffffffffu, idx, j);
            }
            bool iAmLow = ((t & j) == 0);
            bool mineLess = lexless(v, idx, pv, pidx);
            bool takePartner = (mineLess != (iAmLow == up));
            if (takePartner){ v = pv; idx = pidx; }
        }
    }

    // ---- stage D: multiplicative exclusive scan of sorted values ----
    {
        int lane = t & 31, warp = t >> 5;
        float p = v;
        #pragma unroll
        for (int d=1; d<32; d<<=1){
            float q = __shfl_up_sync(0xffffffffu, p, d);
            if (lane >= d) p *= q;
        }
        if (lane==31) wp[warp] = p;
        __syncthreads();
        if (t < 32){
            float q = wp[t];
            #pragma unroll
            for (int d=1; d<32; d<<=1){
                float z = __shfl_up_sync(0xffffffffu, q, d);
                if (t >= d) q *= z;
            }
            wscan[t] = q;
        }
        __syncthreads();
        float prefix = (warp==0)? 1.f : wscan[warp-1];
        float exw = __shfl_up_sync(0xffffffffu, p, 1);
        if (lane==0) exw = 1.f;
        float excl = exw * prefix;
        tbuf[idx] = (1.f - v) * excl;   // scatter to original order
    }
    __syncthreads();

    // ---- stage E: write-content softmax + ww ----
    float beta = act[324];
    float s = g_simw[b*NN+t]*beta;
    float m = s;
    #pragma unroll
    for (int mm=16;mm;mm>>=1) m = fmaxf(m, __shfl_xor_sync(0xffffffffu,m,mm));
    if ((t&31)==0) red[t>>5]=m;
    __syncthreads();
    if (t==0){ float z=red[0]; for (int i=1;i<32;i++) z=fmaxf(z,red[i]); red[0]=z; }
    __syncthreads();
    m = red[0];
    float e = expf(s-m);
    float ssum = e;
    #pragma unroll
    for (int mm=16;mm;mm>>=1) ssum += __shfl_xor_sync(0xffffffffu,ssum,mm);
    __syncthreads();
    if ((t&31)==0) red[t>>5]=ssum;
    __syncthreads();
    if (t==0){ float z=0.f; for (int i=0;i<32;i++) z+=red[i]; red[0]=z; }
    __syncthreads();
    float wcw = e/red[0];
    float ag = act[457], wg = act[458];
    g_ww[b*NN+t] = wg*(ag*tbuf[t] + (1.f-ag)*wcw);
    g_Ldiag[b*NN+t] = link[((size_t)b*NN + t)*NN + t];
}

// ================= K4: chunk-interleaved link matvecs + fused newmem blocks =====
// grid (BB, 17): y<16 = R4-proven linkmv strip; y==16 = newmem for batch b.
union SmemU {
    struct { u64 e01[NN], e23[NN], f01[NN], f23[NN]; } l;       // 32KB
    struct { float tile[128][65]; float er[64], wv[64], rk[256]; } n; // ~35KB
};

__global__ void __launch_bounds__(256) k_linkmv(const float* __restrict__ link,
                                                const float* __restrict__ rw,
                                                const float* __restrict__ mem){
    __shared__ SmemU sm;
    int b = blockIdx.x, s = blockIdx.y;
    int t = threadIdx.x;

    if (s == 16){
        // ---------- newmem path: new memory + read-content sims for batch b ------
        if (t < 64){ sm.n.er[t]=g_erase[b*64+t]; sm.n.wv[t]=g_wv[b*64+t]; }
        if (t < 256) sm.n.rk[t]=g_rk_n[b*256+t];
        const float2* m2 = reinterpret_cast<const float2*>(mem);
        float2* o2 = reinterpret_cast<float2*>(g_nm);
        for (int p=0; p<8; p++){
            int row0 = p*128;
            __syncthreads();
            #pragma unroll
            for (int idx=t; idx<128*32; idx+=256){
                int row = idx>>5, c2 = idx&31;
                float2 v = m2[((size_t)b*NN + row0+row)*32 + c2];
                sm.n.tile[row][c2*2]=v.x; sm.n.tile[row][c2*2+1]=v.y;
            }
            __syncthreads();
            if (t < 128){
                int n = row0 + t;
                float wwn = g_ww[b*NN+n];
                float nsq=0.f, d0=0.f, d1=0.f, d2=0.f, d3=0.f;
                #pragma unroll
                for (int w=0;w<64;w++){
                    float nv = sm.n.tile[t][w]*(1.f - wwn*sm.n.er[w]) + wwn*sm.n.wv[w];
                    sm.n.tile[t][w] = nv;
                    nsq += nv*nv;
                    d0  += nv*sm.n.rk[0*64+w];
                    d1  += nv*sm.n.rk[1*64+w];
                    d2  += nv*sm.n.rk[2*64+w];
                    d3  += nv*sm.n.rk[3*64+w];
                }
                float inv = 1.f/(sqrtf(nsq)+DELTA);
                g_simr[(b*4+0)*NN+n]=d0*inv;
                g_simr[(b*4+1)*NN+n]=d1*inv;
                g_simr[(b*4+2)*NN+n]=d2*inv;
                g_simr[(b*4+3)*NN+n]=d3*inv;
            }
            __syncthreads();
            #pragma unroll
            for (int idx=t; idx<128*32; idx+=256){
                int row = idx>>5, c2 = idx&31;
                o2[((size_t)b*NN + row0+row)*32 + c2] =
                    make_float2(sm.n.tile[row][c2*2], sm.n.tile[row][c2*2+1]);
            }
        }
        return;
    }

    // ---------- linkmv path (R12 / R4-proven) ----------
    u64* e01 = sm.l.e01; u64* e23 = sm.l.e23; u64* f01 = sm.l.f01; u64* f23 = sm.l.f23;
    for (int n=t;n<NN;n+=256){
        float r0=rw[(b*4+0)*NN+n], r1=rw[(b*4+1)*NN+n];
        float r2=rw[(b*4+2)*NN+n], r3=rw[(b*4+3)*NN+n];
        float w = g_ww[b*NN+n];
        e01[n]=pack2(r0,r1); e23[n]=pack2(r2,r3);
        f01[n]=pack2(r0*w,r1*w); f23[n]=pack2(r2*w,r3*w);
    }
    __syncthreads();
    const float* Lb = link + (size_t)b*NN*NN;
    int i0 = s*STRIP;
    int wid = t>>5, lane = t&31;

    u64 T1a[4], T1b[4], T2a[4], T2b[4];
    #pragma unroll
    for (int c=0;c<4;c++){ T1a[c]=0ull; T1b[c]=0ull; T2a[c]=0ull; T2b[c]=0ull; }

    #pragma unroll
    for (int ch=0; ch<2; ch++){
        int c0 = i0 + ch*32;
        // ---- phase T: stream 32 rows (128KB) from DRAM ----
        #pragma unroll 2
        for (int i=0;i<32;i+=4){
            float4 lv[4];
            #pragma unroll
            for (int k=0;k<4;k++)
                lv[k] = reinterpret_cast<const float4*>(Lb + (size_t)(c0+i+k)*NN)[t];
            #pragma unroll
            for (int k=0;k<4;k++){
                int row = c0+i+k;
                u64 ca=e01[row], cb=e23[row], cc=f01[row], cd=f23[row];
                float l[4] = {lv[k].x, lv[k].y, lv[k].z, lv[k].w};
                #pragma unroll
                for (int c=0;c<4;c++){
                    u64 p = pack2(l[c], l[c]);
                    fma2(T1a[c],p,ca); fma2(T1b[c],p,cb);
                    fma2(T2a[c],p,cc); fma2(T2b[c],p,cd);
                }
            }
        }
        __syncthreads();
        // ---- phase S: rows of this chunk, reading L2-hot lines ----
        {
            int r0i = c0 + wid*4;
            u64 acc[4][4];
            #pragma unroll
            for (int a=0;a<4;a++)
                #pragma unroll
                for (int c=0;c<4;c++) acc[a][c]=0ull;
            const float* L0 = Lb + (size_t)r0i*NN + lane;
            #pragma unroll 4
            for (int it=0; it<32; it++){
                int j = it*32 + lane;
                float lv0=L0[it*32];
                float lv1=L0[it*32+NN];
                float lv2=L0[it*32+2*NN];
                float lv3=L0[it*32+3*NN];
                u64 ca=e01[j], cb=e23[j], cc=f01[j], cd=f23[j];
                u64 p0=pack2(lv0,lv0), p1=pack2(lv1,lv1), p2=pack2(lv2,lv2), p3=pack2(lv3,lv3);
                fma2(acc[0][0],p0,ca); fma2(acc[0][1],p0,cb); fma2(acc[0][2],p0,cc); fma2(acc[0][3],p0,cd);
                fma2(acc[1][0],p1,ca); fma2(acc[1][1],p1,cb); fma2(acc[1][2],p1,cc); fma2(acc[1][3],p1,cd);
                fma2(acc[2][0],p2,ca); fma2(acc[2][1],p2,cb); fma2(acc[2][2],p2,cc); fma2(acc[2][3],p2,cd);
                fma2(acc[3][0],p3,ca); fma2(acc[3][1],p3,cb); fma2(acc[3][2],p3,cc); fma2(acc[3][3],p3,cd);
            }
            #pragma unroll
            for (int row=0;row<4;row++)
                #pragma unroll
                for (int c=0;c<4;c++)
                    #pragma unroll
                    for (int m=16;m;m>>=1)
                        acc[row][c] = add2(acc[row][c], __shfl_xor_sync(0xffffffffu, acc[row][c], m));
            if (lane==0){
                #pragma unroll
                for (int row=0;row<4;row++){
                    int i = r0i+row;
                    float lo,hi;
                    unpack2(acc[row][0],lo,hi); g_S1[(b*4+0)*NN+i]=lo; g_S1[(b*4+1)*NN+i]=hi;
                    unpack2(acc[row][1],lo,hi); g_S1[(b*4+2)*NN+i]=lo; g_S1[(b*4+3)*NN+i]=hi;
                    unpack2(acc[row][2],lo,hi); g_S2[(b*4+0)*NN+i]=lo; g_S2[(b*4+1)*NN+i]=hi;
                    unpack2(acc[row][3],lo,hi); g_S2[(b*4+2)*NN+i]=lo; g_S2[(b*4+3)*NN+i]=hi;
                }
            }
        }
    }

    // ---- write T strip partials (float4 coalesced) ----
    float lo[4], hi[4];
    float4* tp;
    #pragma unroll
    for (int c=0;c<4;c++) unpack2(T1a[c], lo[c], hi[c]);
    tp = reinterpret_cast<float4*>(&g_Tp[b][s][0][0]); tp[t] = make_float4(lo[0],lo[1],lo[2],lo[3]);
    tp = reinterpret_cast<float4*>(&g_Tp[b][s][1][0]); tp[t] = make_float4(hi[0],hi[1],hi[2],hi[3]);
    #pragma unroll
    for (int c=0;c<4;c++) unpack2(T1b[c], lo[c], hi[c]);
    tp = reinterpret_cast<float4*>(&g_Tp[b][s][2][0]); tp[t] = make_float4(lo[0],lo[1],lo[2],lo[3]);
    tp = reinterpret_cast<float4*>(&g_Tp[b][s][3][0]); tp[t] = make_float4(hi[0],hi[1],hi[2],hi[3]);
    #pragma unroll
    for (int c=0;c<4;c++) unpack2(T2a[c], lo[c], hi[c]);
    tp = reinterpret_cast<float4*>(&g_Tp[b][s][4][0]); tp[t] = make_float4(lo[0],lo[1],lo[2],lo[3]);
    tp = reinterpret_cast<float4*>(&g_Tp[b][s][5][0]); tp[t] = make_float4(hi[0],hi[1],hi[2],hi[3]);
    #pragma unroll
    for (int c=0;c<4;c++) unpack2(T2b[c], lo[c], hi[c]);
    tp = reinterpret_cast<float4*>(&g_Tp[b][s][6][0]); tp[t] = make_float4(lo[0],lo[1],lo[2],lo[3]);
    tp = reinterpret_cast<float4*>(&g_Tp[b][s][7][0]); tp[t] = make_float4(hi[0],hi[1],hi[2],hi[3]);
}

// ================= K6: assembly + output (R4 proven) ==========================
__device__ __forceinline__ float blockSum512(float v, float* red){
    int t=threadIdx.x;
    #pragma unroll
    for (int m=16;m;m>>=1) v += __shfl_xor_sync(0xffffffffu,v,m);
    __syncthreads();
    if ((t&31)==0) red[t>>5]=v;
    __syncthreads();
    if (t==0){ float z=0.f; for (int i=0;i<16;i++) z+=red[i]; red[0]=z; }
    __syncthreads();
    float r = red[0];
    __syncthreads();
    return r;
}
__device__ __forceinline__ float blockMax512(float v, float* red){
    int t=threadIdx.x;
    #pragma unroll
    for (int m=16;m;m>>=1) v = fmaxf(v, __shfl_xor_sync(0xffffffffu,v,m));
    __syncthreads();
    if ((t&31)==0) red[t>>5]=v;
    __syncthreads();
    if (t==0){ float z=red[0]; for (int i=1;i<16;i++) z=fmaxf(z,red[i]); red[0]=z; }
    __syncthreads();
    float r = red[0];
    __syncthreads();
    return r;
}

__global__ void __launch_bounds__(512) k_read(const float* __restrict__ prec,
                                              const float* __restrict__ rw,
                                              float* __restrict__ out){
    int b = blockIdx.x, r = blockIdx.y;
    int t = threadIdx.x;
    int br = b*4+r;
    __shared__ float nrw[NN];
    __shared__ float pout[512];
    __shared__ float red[16];
    float s1[2],s2[2],t1[2],t2[2],wwv[2],pv[2],rv[2],ldv[2],sv[2];
    float beta = g_rstr[br];
    float dpart=0.f, epart=0.f, mpart=-1e30f;
    #pragma unroll
    for (int k=0;k<2;k++){
        int n = t + k*512;
        s1[k]=g_S1[br*NN+n]; s2[k]=g_S2[br*NN+n];
        float a1=0.f, a2=0.f;
        #pragma unroll 8
        for (int st=0; st<NSTRIPS; st++){
            a1 += g_Tp[b][st][r][n];
            a2 += g_Tp[b][st][4+r][n];
        }
        t1[k]=a1; t2[k]=a2;
        wwv[k]=g_ww[b*NN+n]; pv[k]=prec[b*NN+n];
        rv[k]=rw[br*NN+n];   ldv[k]=g_Ldiag[b*NN+n];
        sv[k]=g_simr[br*NN+n]*beta;
        dpart += pv[k]*rv[k];
        epart += wwv[k]*rv[k];
        mpart = fmaxf(mpart, sv[k]);
    }
    float D = blockSum512(dpart, red);
    float E = blockSum512(epart, red);
    float M = blockMax512(mpart, red);
    float ex[2]; float spart=0.f;
    #pragma unroll
    for (int k=0;k<2;k++){ ex[k]=expf(sv[k]-M); spart+=ex[k]; }
    float S = blockSum512(spart, red);
    float invS = 1.f/S;
    float rm0=g_rm[b*12+r*3+0], rm1=g_rm[b*12+r*3+1], rm2=g_rm[b*12+r*3+2];
    #pragma unroll
    for (int k=0;k<2;k++){
        int n = t + k*512;
        float w = wwv[k];
        float diag = ((1.f-2.f*w)*ldv[k] + w*pv[k])*rv[k];
        float fwd = (1.f-w)*s1[k] - s2[k] + w*D - diag;
        float bwd = (1.f-w)*t1[k] - t2[k] + pv[k]*E - diag;
        float crw = ex[k]*invS;
        nrw[n] = rm0*bwd + rm1*crw + rm2*fwd;
    }
    __syncthreads();
    int w = t & 63, chunk = t >> 6;
    const float* nm = g_nm + (size_t)b*NN*WL;
    float a0=0.f,a1=0.f,a2=0.f,a3=0.f;
    int n0 = chunk*128;
    for (int n=n0; n<n0+128; n+=4){
        a0 = fmaf(nrw[n  ], nm[(size_t)(n  )*WL + w], a0);
        a1 = fmaf(nrw[n+1], nm[(size_t)(n+1)*WL + w], a1);
        a2 = fmaf(nrw[n+2], nm[(size_t)(n+2)*WL + w], a2);
        a3 = fmaf(nrw[n+3], nm[(size_t)(n+3)*WL + w], a3);
    }
    pout[t] = (a0+a1)+(a2+a3);
    __syncthreads();
    if (t < 64){
        float s = 0.f;
        #pragma unroll
        for (int c=0;c<8;c++) s += pout[c*64+t];
        out[br*64+t] = s;
    }
}

// ================= launch =================
extern "C" void kernel_launch(void* const* d_in, const int* in_sizes, int n_in,
                              void* d_out, int out_size){
    const float* x     = (const float*)d_in[0];
    const float* W     = (const float*)d_in[1];
    const float* bias  = (const float*)d_in[2];
    const float* mem   = (const float*)d_in[3];
    const float* link  = (const float*)d_in[4];
    const float* prec  = (const float*)d_in[5];
    const float* rw    = (const float*)d_in[6];
    const float* wwold = (const float*)d_in[7];
    const float* usage = (const float*)d_in[8];
    float* out = (float*)d_out;

    k_gemm<<<dim3(15, KSLICES), 256>>>(x, W);
    k_simw<<<dim3(BB, 8), 128>>>(mem, bias);
    k_alloc<<<BB, 1024>>>(bias, usage, wwold, rw, link);
    k_linkmv<<<dim3(BB, NSTRIPS+1), 256>>>(link, rw, mem);
    k_read<<<dim3(BB,RR), 512>>>(prec, rw, out);
}

// round 16
// speedup vs baseline: 1.1196x; 1.1170x over previous
#include <cuda_runtime.h>
#include <stdint.h>
#include <math.h>

#define BB 32
#define NINPUT 1024
#define NN 1024
#define WL 64
#define RR 4
#define IFACE 471
#define OPAD 480
#define KSLICES 8
#define NSTRIPS 16
#define STRIP 64
#define DELTA 1e-6f

typedef unsigned long long u64;

// ---------------- scratch (static device memory; no allocation) ----------------
__device__ float g_xi_part[KSLICES][BB][OPAD];
__device__ float g_rk_n[BB*RR*WL];
__device__ float g_rstr[BB*RR];
__device__ float g_erase[BB*WL];
__device__ float g_wv[BB*WL];
__device__ float g_rm[BB*RR*3];
__device__ float g_simw[BB*NN];
__device__ float g_ww[BB*NN];
__device__ float g_Ldiag[BB*NN];
__device__ float g_S1[BB*RR*NN];
__device__ float g_S2[BB*RR*NN];
__device__ float g_Tp[BB][NSTRIPS][8][NN];   // T strip partials (16 MB)
__device__ float g_nm[BB*NN*WL];
__device__ float g_simr[BB*RR*NN];

// ---------------- helpers ----------------
__device__ __forceinline__ float sigmoidf_(float x){ return 1.f/(1.f+expf(-x)); }
__device__ __forceinline__ float softplusf_(float x){ return fmaxf(x,0.f)+log1pf(expf(-fabsf(x))); }

__device__ __forceinline__ u64 pack2(float a, float b){
    u64 r; asm("mov.b64 %0,{%1,%2};":"=l"(r):"f"(a),"f"(b)); return r;
}
__device__ __forceinline__ void unpack2(u64 v, float& a, float& b){
    asm("mov.b64 {%0,%1},%2;":"=f"(a),"=f"(b):"l"(v));
}
__device__ __forceinline__ void fma2(u64& d, u64 a, u64 b){
    asm("fma.rn.f32x2 %0,%1,%2,%0;":"+l"(d):"l"(a),"l"(b));
}
__device__ __forceinline__ u64 add2(u64 a, u64 b){
    u64 r; asm("add.rn.f32x2 %0,%1,%2;":"=l"(r):"l"(a),"l"(b)); return r;
}

// ================= K1: interface GEMM (tiled, k-sliced partials) =================
__global__ void __launch_bounds__(256) k_gemm(const float* __restrict__ x,
                                              const float* __restrict__ W){
    int otile = blockIdx.x, ks = blockIdx.y;
    int t = threadIdx.x;
    __shared__ float ws[128][32];
    __shared__ float xs[32][128];
    int o0 = otile*32, k0 = ks*128;
    {
        int oo = t & 31, r0 = t >> 5;
        int o = o0 + oo;
        for (int r = r0; r < 128; r += 8)
            ws[r][oo] = (o < IFACE) ? W[(size_t)(k0 + r)*IFACE + o] : 0.f;
    }
    {
        int kk = t & 127, b0 = t >> 7;
        for (int b = b0; b < 32; b += 2)
            xs[b][kk] = x[b*NINPUT + k0 + kk];
    }
    __syncthreads();
    int p = t & 15;
    int b0 = (t >> 4)*2;
    u64 a0 = 0ull, a1 = 0ull;
    #pragma unroll 8
    for (int kk = 0; kk < 128; kk++){
        u64 wp = *reinterpret_cast<const u64*>(&ws[kk][p*2]);
        float xb0 = xs[b0][kk], xb1 = xs[b0+1][kk];
        fma2(a0, wp, pack2(xb0,xb0));
        fma2(a1, wp, pack2(xb1,xb1));
    }
    float f0,f1;
    unpack2(a0,f0,f1);
    g_xi_part[ks][b0  ][o0+p*2]=f0; g_xi_part[ks][b0  ][o0+p*2+1]=f1;
    unpack2(a1,f0,f1);
    g_xi_part[ks][b0+1][o0+p*2]=f0; g_xi_part[ks][b0+1][o0+p*2+1]=f1;
}

// ================= K2: write content similarity (staged transpose, coalesced) ====
__global__ void __launch_bounds__(128) k_simw(const float* __restrict__ mem,
                                              const float* __restrict__ bias){
    int b = blockIdx.x;
    int t = threadIdx.x;
    int row0 = blockIdx.y*128;
    __shared__ float tile[128][65];
    __shared__ float wk[64];
    __shared__ float invwk;
    if (t < 64){
        float acc = bias[260+t];
        #pragma unroll
        for (int ks=0; ks<KSLICES; ks++) acc += g_xi_part[ks][b][260+t];
        wk[t] = tanhf(acc);
    }
    __syncthreads();
    if (t < 32){
        float s = wk[t]*wk[t] + wk[t+32]*wk[t+32];
        #pragma unroll
        for (int m=16;m;m>>=1) s += __shfl_xor_sync(0xffffffffu, s, m);
        if (t==0) invwk = 1.f/(sqrtf(s)+DELTA);
    }
    const float2* m2 = reinterpret_cast<const float2*>(mem);
    #pragma unroll
    for (int idx=t; idx<128*32; idx+=128){
        int row = idx>>5, c2 = idx&31;
        float2 v = m2[((size_t)b*NN + row0+row)*32 + c2];
        tile[row][c2*2]=v.x; tile[row][c2*2+1]=v.y;
    }
    __syncthreads();
    int n = row0 + t;
    float nsq=0.f, dot=0.f;
    #pragma unroll
    for (int w=0;w<64;w++){
        float v = tile[t][w];
        nsq += v*v;
        dot += v*wk[w];
    }
    g_simw[b*NN+n] = dot / (sqrtf(nsq)+DELTA) * invwk;
}

// ================= K3: act + usage + bitonic argsort + scan + ww ==============
__device__ __forceinline__ bool lexless(float va, int ia, float vb, int ib){
    return (va < vb) || (va == vb && ia < ib);
}

__global__ void __launch_bounds__(1024) k_alloc(const float* __restrict__ bias,
                        const float* __restrict__ usage, const float* __restrict__ wwold,
                        const float* __restrict__ rw, const float* __restrict__ link){
    int b = blockIdx.x; int t = threadIdx.x; // 1024 threads
    __shared__ float act[IFACE+1];
    __shared__ float norms[4];
    __shared__ float sv[NN];
    __shared__ int   si[NN];
    __shared__ float tbuf[NN];
    __shared__ float red[32];
    __shared__ float wp[32], wscan[32];

    // ---- stage A: activations ----
    if (t < IFACE){
        float acc = bias[t];
        #pragma unroll
        for (int ks=0; ks<KSLICES; ks++) acc += g_xi_part[ks][b][t];
        float v;
        if (t < 256)       v = tanhf(acc);
        else if (t < 260)  v = softplusf_(acc);
        else if (t < 324)  v = tanhf(acc);
        else if (t == 324) v = softplusf_(acc);
        else if (t < 389)  v = sigmoidf_(acc);
        else if (t < 453)  v = tanhf(acc);
        else if (t < 459)  v = sigmoidf_(acc);
        else               v = acc;
        act[t] = v;
    }
    __syncthreads();
    if (t < 128){
        int g = t>>5, l = t&31;
        const float* base = act + g*64;
        float s = base[l]*base[l] + base[l+32]*base[l+32];
        #pragma unroll
        for (int m=16;m;m>>=1) s += __shfl_xor_sync(0xffffffffu, s, m);
        if (l==0) norms[g] = sqrtf(s) + DELTA;
    }
    __syncthreads();
    if (t < 256)       g_rk_n[b*256+t] = act[t] / norms[t>>6];
    else if (t < 260)  g_rstr[b*4 + (t-256)] = act[t];
    else if (t >= 325 && t < 389)  g_erase[b*64 + (t-325)] = act[t];
    else if (t >= 389 && t < 453)  g_wv[b*64 + (t-389)] = act[t];
    if (t < 4){
        float a0=act[459+t*3], a1=act[460+t*3], a2=act[461+t*3];
        float mx=fmaxf(a0,fmaxf(a1,a2));
        float e0=expf(a0-mx), e1=expf(a1-mx), e2=expf(a2-mx);
        float inv=1.f/(e0+e1+e2);
        g_rm[b*12+t*3+0]=e0*inv; g_rm[b*12+t*3+1]=e1*inv; g_rm[b*12+t*3+2]=e2*inv;
    }

    // ---- stage B: usage ----
    float us = usage[b*NN+t];
    float u = us + (1.f-us)*wwold[b*NN+t];
    float psi = 1.f;
    #pragma unroll
    for (int r=0;r<4;r++) psi *= (1.f - act[453+r]*rw[(b*4+r)*NN+t]);
    u *= psi;
    u = DELTA + (1.f-DELTA)*u;

    // ---- stage C: bitonic argsort on (value, index), shfl for j<=16 ----
    float v = u; int idx = t;
    for (int k=2;k<=NN;k<<=1){
        bool up = ((t & k)==0);
        for (int j=k>>1;j>0;j>>=1){
            float pv; int pidx;
            if (j >= 32){
                sv[t]=v; si[t]=idx;
                __syncthreads();
                pv = sv[t^j]; pidx = si[t^j];
                __syncthreads();
            } else {
                pv   = __shfl_xor_sync(0xffffffffu, v, j);
                pidx = __shfl_xor_sync(0xffffffffu, idx, j);
            }
            bool iAmLow = ((t & j) == 0);
            bool mineLess = lexless(v, idx, pv, pidx);
            bool takePartner = (mineLess != (iAmLow == up));
            if (takePartner){ v = pv; idx = pidx; }
        }
    }

    // ---- stage D: multiplicative exclusive scan of sorted values ----
    {
        int lane = t & 31, warp = t >> 5;
        float p = v;
        #pragma unroll
        for (int d=1; d<32; d<<=1){
            float q = __shfl_up_sync(0xffffffffu, p, d);
            if (lane >= d) p *= q;
        }
        if (lane==31) wp[warp] = p;
        __syncthreads();
        if (t < 32){
            float q = wp[t];
            #pragma unroll
            for (int d=1; d<32; d<<=1){
                float z = __shfl_up_sync(0xffffffffu, q, d);
                if (t >= d) q *= z;
            }
            wscan[t] = q;
        }
        __syncthreads();
        float prefix = (warp==0)? 1.f : wscan[warp-1];
        float exw = __shfl_up_sync(0xffffffffu, p, 1);
        if (lane==0) exw = 1.f;
        float excl = exw * prefix;
        tbuf[idx] = (1.f - v) * excl;   // scatter to original order
    }
    __syncthreads();

    // ---- stage E: write-content softmax + ww ----
    float beta = act[324];
    float s = g_simw[b*NN+t]*beta;
    float m = s;
    #pragma unroll
    for (int mm=16;mm;mm>>=1) m = fmaxf(m, __shfl_xor_sync(0xffffffffu,m,mm));
    if ((t&31)==0) red[t>>5]=m;
    __syncthreads();
    if (t==0){ float z=red[0]; for (int i=1;i<32;i++) z=fmaxf(z,red[i]); red[0]=z; }
    __syncthreads();
    m = red[0];
    float e = expf(s-m);
    float ssum = e;
    #pragma unroll
    for (int mm=16;mm;mm>>=1) ssum += __shfl_xor_sync(0xffffffffu,ssum,mm);
    __syncthreads();
    if ((t&31)==0) red[t>>5]=ssum;
    __syncthreads();
    if (t==0){ float z=0.f; for (int i=0;i<32;i++) z+=red[i]; red[0]=z; }
    __syncthreads();
    float wcw = e/red[0];
    float ag = act[457], wg = act[458];
    g_ww[b*NN+t] = wg*(ag*tbuf[t] + (1.f-ag)*wcw);
    g_Ldiag[b*NN+t] = link[((size_t)b*NN + t)*NN + t];
}

// ================= K4: chunk-interleaved link matvecs + fused newmem slabs ======
// grid (BB, 24): y<16 = R4-proven linkmv strip; y in [16,24) = newmem for one
// 128-row slab of batch b (fine granularity -> fills wave gaps, never the tail).
union SmemU {
    struct { u64 e01[NN], e23[NN], f01[NN], f23[NN]; } l;       // 32KB
    struct { float tile[128][65]; float er[64], wv[64], rk[256]; } n; // ~35KB
};

__global__ void __launch_bounds__(256) k_linkmv(const float* __restrict__ link,
                                                const float* __restrict__ rw,
                                                const float* __restrict__ mem){
    __shared__ SmemU sm;
    int b = blockIdx.x, s = blockIdx.y;
    int t = threadIdx.x;

    if (s >= 16){
        // ---------- newmem path: one 128-row slab ----------
        int row0 = (s-16)*128;
        if (t < 64){ sm.n.er[t]=g_erase[b*64+t]; sm.n.wv[t]=g_wv[b*64+t]; }
        sm.n.rk[t]=g_rk_n[b*256+t];
        const float2* m2 = reinterpret_cast<const float2*>(mem);
        float2* o2 = reinterpret_cast<float2*>(g_nm);
        __syncthreads();
        #pragma unroll
        for (int idx=t; idx<128*32; idx+=256){
            int row = idx>>5, c2 = idx&31;
            float2 v = m2[((size_t)b*NN + row0+row)*32 + c2];
            sm.n.tile[row][c2*2]=v.x; sm.n.tile[row][c2*2+1]=v.y;
        }
        __syncthreads();
        if (t < 128){
            int n = row0 + t;
            float wwn = g_ww[b*NN+n];
            float nsq=0.f, d0=0.f, d1=0.f, d2=0.f, d3=0.f;
            #pragma unroll
            for (int w=0;w<64;w++){
                float nv = sm.n.tile[t][w]*(1.f - wwn*sm.n.er[w]) + wwn*sm.n.wv[w];
                sm.n.tile[t][w] = nv;
                nsq += nv*nv;
                d0  += nv*sm.n.rk[0*64+w];
                d1  += nv*sm.n.rk[1*64+w];
                d2  += nv*sm.n.rk[2*64+w];
                d3  += nv*sm.n.rk[3*64+w];
            }
            float inv = 1.f/(sqrtf(nsq)+DELTA);
            g_simr[(b*4+0)*NN+n]=d0*inv;
            g_simr[(b*4+1)*NN+n]=d1*inv;
            g_simr[(b*4+2)*NN+n]=d2*inv;
            g_simr[(b*4+3)*NN+n]=d3*inv;
        }
        __syncthreads();
        #pragma unroll
        for (int idx=t; idx<128*32; idx+=256){
            int row = idx>>5, c2 = idx&31;
            o2[((size_t)b*NN + row0+row)*32 + c2] =
                make_float2(sm.n.tile[row][c2*2], sm.n.tile[row][c2*2+1]);
        }
        return;
    }

    // ---------- linkmv path (R12 / R4-proven) ----------
    u64* e01 = sm.l.e01; u64* e23 = sm.l.e23; u64* f01 = sm.l.f01; u64* f23 = sm.l.f23;
    for (int n=t;n<NN;n+=256){
        float r0=rw[(b*4+0)*NN+n], r1=rw[(b*4+1)*NN+n];
        float r2=rw[(b*4+2)*NN+n], r3=rw[(b*4+3)*NN+n];
        float w = g_ww[b*NN+n];
        e01[n]=pack2(r0,r1); e23[n]=pack2(r2,r3);
        f01[n]=pack2(r0*w,r1*w); f23[n]=pack2(r2*w,r3*w);
    }
    __syncthreads();
    const float* Lb = link + (size_t)b*NN*NN;
    int i0 = s*STRIP;
    int wid = t>>5, lane = t&31;

    u64 T1a[4], T1b[4], T2a[4], T2b[4];
    #pragma unroll
    for (int c=0;c<4;c++){ T1a[c]=0ull; T1b[c]=0ull; T2a[c]=0ull; T2b[c]=0ull; }

    #pragma unroll
    for (int ch=0; ch<2; ch++){
        int c0 = i0 + ch*32;
        // ---- phase T: stream 32 rows (128KB) from DRAM ----
        #pragma unroll 2
        for (int i=0;i<32;i+=4){
            float4 lv[4];
            #pragma unroll
            for (int k=0;k<4;k++)
                lv[k] = reinterpret_cast<const float4*>(Lb + (size_t)(c0+i+k)*NN)[t];
            #pragma unroll
            for (int k=0;k<4;k++){
                int row = c0+i+k;
                u64 ca=e01[row], cb=e23[row], cc=f01[row], cd=f23[row];
                float l[4] = {lv[k].x, lv[k].y, lv[k].z, lv[k].w};
                #pragma unroll
                for (int c=0;c<4;c++){
                    u64 p = pack2(l[c], l[c]);
                    fma2(T1a[c],p,ca); fma2(T1b[c],p,cb);
                    fma2(T2a[c],p,cc); fma2(T2b[c],p,cd);
                }
            }
        }
        __syncthreads();
        // ---- phase S: rows of this chunk, reading L2-hot lines ----
        {
            int r0i = c0 + wid*4;
            u64 acc[4][4];
            #pragma unroll
            for (int a=0;a<4;a++)
                #pragma unroll
                for (int c=0;c<4;c++) acc[a][c]=0ull;
            const float* L0 = Lb + (size_t)r0i*NN + lane;
            #pragma unroll 4
            for (int it=0; it<32; it++){
                int j = it*32 + lane;
                float lv0=L0[it*32];
                float lv1=L0[it*32+NN];
                float lv2=L0[it*32+2*NN];
                float lv3=L0[it*32+3*NN];
                u64 ca=e01[j], cb=e23[j], cc=f01[j], cd=f23[j];
                u64 p0=pack2(lv0,lv0), p1=pack2(lv1,lv1), p2=pack2(lv2,lv2), p3=pack2(lv3,lv3);
                fma2(acc[0][0],p0,ca); fma2(acc[0][1],p0,cb); fma2(acc[0][2],p0,cc); fma2(acc[0][3],p0,cd);
                fma2(acc[1][0],p1,ca); fma2(acc[1][1],p1,cb); fma2(acc[1][2],p1,cc); fma2(acc[1][3],p1,cd);
                fma2(acc[2][0],p2,ca); fma2(acc[2][1],p2,cb); fma2(acc[2][2],p2,cc); fma2(acc[2][3],p2,cd);
                fma2(acc[3][0],p3,ca); fma2(acc[3][1],p3,cb); fma2(acc[3][2],p3,cc); fma2(acc[3][3],p3,cd);
            }
            #pragma unroll
            for (int row=0;row<4;row++)
                #pragma unroll
                for (int c=0;c<4;c++)
                    #pragma unroll
                    for (int m=16;m;m>>=1)
                        acc[row][c] = add2(acc[row][c], __shfl_xor_sync(0xffffffffu, acc[row][c], m));
            if (lane==0){
                #pragma unroll
                for (int row=0;row<4;row++){
                    int i = r0i+row;
                    float lo,hi;
                    unpack2(acc[row][0],lo,hi); g_S1[(b*4+0)*NN+i]=lo; g_S1[(b*4+1)*NN+i]=hi;
                    unpack2(acc[row][1],lo,hi); g_S1[(b*4+2)*NN+i]=lo; g_S1[(b*4+3)*NN+i]=hi;
                    unpack2(acc[row][2],lo,hi); g_S2[(b*4+0)*NN+i]=lo; g_S2[(b*4+1)*NN+i]=hi;
                    unpack2(acc[row][3],lo,hi); g_S2[(b*4+2)*NN+i]=lo; g_S2[(b*4+3)*NN+i]=hi;
                }
            }
        }
    }

    // ---- write T strip partials (float4 coalesced) ----
    float lo[4], hi[4];
    float4* tp;
    #pragma unroll
    for (int c=0;c<4;c++) unpack2(T1a[c], lo[c], hi[c]);
    tp = reinterpret_cast<float4*>(&g_Tp[b][s][0][0]); tp[t] = make_float4(lo[0],lo[1],lo[2],lo[3]);
    tp = reinterpret_cast<float4*>(&g_Tp[b][s][1][0]); tp[t] = make_float4(hi[0],hi[1],hi[2],hi[3]);
    #pragma unroll
    for (int c=0;c<4;c++) unpack2(T1b[c], lo[c], hi[c]);
    tp = reinterpret_cast<float4*>(&g_Tp[b][s][2][0]); tp[t] = make_float4(lo[0],lo[1],lo[2],lo[3]);
    tp = reinterpret_cast<float4*>(&g_Tp[b][s][3][0]); tp[t] = make_float4(hi[0],hi[1],hi[2],hi[3]);
    #pragma unroll
    for (int c=0;c<4;c++) unpack2(T2a[c], lo[c], hi[c]);
    tp = reinterpret_cast<float4*>(&g_Tp[b][s][4][0]); tp[t] = make_float4(lo[0],lo[1],lo[2],lo[3]);
    tp = reinterpret_cast<float4*>(&g_Tp[b][s][5][0]); tp[t] = make_float4(hi[0],hi[1],hi[2],hi[3]);
    #pragma unroll
    for (int c=0;c<4;c++) unpack2(T2b[c], lo[c], hi[c]);
    tp = reinterpret_cast<float4*>(&g_Tp[b][s][6][0]); tp[t] = make_float4(lo[0],lo[1],lo[2],lo[3]);
    tp = reinterpret_cast<float4*>(&g_Tp[b][s][7][0]); tp[t] = make_float4(hi[0],hi[1],hi[2],hi[3]);
}

// ================= K6: assembly + output (R4 proven) ==========================
__device__ __forceinline__ float blockSum512(float v, float* red){
    int t=threadIdx.x;
    #pragma unroll
    for (int m=16;m;m>>=1) v += __shfl_xor_sync(0xffffffffu,v,m);
    __syncthreads();
    if ((t&31)==0) red[t>>5]=v;
    __syncthreads();
    if (t==0){ float z=0.f; for (int i=0;i<16;i++) z+=red[i]; red[0]=z; }
    __syncthreads();
    float r = red[0];
    __syncthreads();
    return r;
}
__device__ __forceinline__ float blockMax512(float v, float* red){
    int t=threadIdx.x;
    #pragma unroll
    for (int m=16;m;m>>=1) v = fmaxf(v, __shfl_xor_sync(0xffffffffu,v,m));
    __syncthreads();
    if ((t&31)==0) red[t>>5]=v;
    __syncthreads();
    if (t==0){ float z=red[0]; for (int i=1;i<16;i++) z=fmaxf(z,red[i]); red[0]=z; }
    __syncthreads();
    float r = red[0];
    __syncthreads();
    return r;
}

__global__ void __launch_bounds__(512) k_read(const float* __restrict__ prec,
                                              const float* __restrict__ rw,
                                              float* __restrict__ out){
    int b = blockIdx.x, r = blockIdx.y;
    int t = threadIdx.x;
    int br = b*4+r;
    __shared__ float nrw[NN];
    __shared__ float pout[512];
    __shared__ float red[16];
    float s1[2],s2[2],t1[2],t2[2],wwv[2],pv[2],rv[2],ldv[2],sv[2];
    float beta = g_rstr[br];
    float dpart=0.f, epart=0.f, mpart=-1e30f;
    #pragma unroll
    for (int k=0;k<2;k++){
        int n = t + k*512;
        s1[k]=g_S1[br*NN+n]; s2[k]=g_S2[br*NN+n];
        float a1=0.f, a2=0.f;
        #pragma unroll 8
        for (int st=0; st<NSTRIPS; st++){
            a1 += g_Tp[b][st][r][n];
            a2 += g_Tp[b][st][4+r][n];
        }
        t1[k]=a1; t2[k]=a2;
        wwv[k]=g_ww[b*NN+n]; pv[k]=prec[b*NN+n];
        rv[k]=rw[br*NN+n];   ldv[k]=g_Ldiag[b*NN+n];
        sv[k]=g_simr[br*NN+n]*beta;
        dpart += pv[k]*rv[k];
        epart += wwv[k]*rv[k];
        mpart = fmaxf(mpart, sv[k]);
    }
    float D = blockSum512(dpart, red);
    float E = blockSum512(epart, red);
    float M = blockMax512(mpart, red);
    float ex[2]; float spart=0.f;
    #pragma unroll
    for (int k=0;k<2;k++){ ex[k]=expf(sv[k]-M); spart+=ex[k]; }
    float S = blockSum512(spart, red);
    float invS = 1.f/S;
    float rm0=g_rm[b*12+r*3+0], rm1=g_rm[b*12+r*3+1], rm2=g_rm[b*12+r*3+2];
    #pragma unroll
    for (int k=0;k<2;k++){
        int n = t + k*512;
        float w = wwv[k];
        float diag = ((1.f-2.f*w)*ldv[k] + w*pv[k])*rv[k];
        float fwd = (1.f-w)*s1[k] - s2[k] + w*D - diag;
        float bwd = (1.f-w)*t1[k] - t2[k] + pv[k]*E - diag;
        float crw = ex[k]*invS;
        nrw[n] = rm0*bwd + rm1*crw + rm2*fwd;
    }
    __syncthreads();
    int w = t & 63, chunk = t >> 6;
    const float* nm = g_nm + (size_t)b*NN*WL;
    float a0=0.f,a1=0.f,a2=0.f,a3=0.f;
    int n0 = chunk*128;
    for (int n=n0; n<n0+128; n+=4){
        a0 = fmaf(nrw[n  ], nm[(size_t)(n  )*WL + w], a0);
        a1 = fmaf(nrw[n+1], nm[(size_t)(n+1)*WL + w], a1);
        a2 = fmaf(nrw[n+2], nm[(size_t)(n+2)*WL + w], a2);
        a3 = fmaf(nrw[n+3], nm[(size_t)(n+3)*WL + w], a3);
    }
    pout[t] = (a0+a1)+(a2+a3);
    __syncthreads();
    if (t < 64){
        float s = 0.f;
        #pragma unroll
        for (int c=0;c<8;c++) s += pout[c*64+t];
        out[br*64+t] = s;
    }
}

// ================= launch =================
extern "C" void kernel_launch(void* const* d_in, const int* in_sizes, int n_in,
                              void* d_out, int out_size){
    const float* x     = (const float*)d_in[0];
    const float* W     = (const float*)d_in[1];
    const float* bias  = (const float*)d_in[2];
    const float* mem   = (const float*)d_in[3];
    const float* link  = (const float*)d_in[4];
    const float* prec  = (const float*)d_in[5];
    const float* rw    = (const float*)d_in[6];
    const float* wwold = (const float*)d_in[7];
    const float* usage = (const float*)d_in[8];
    float* out = (float*)d_out;

    k_gemm<<<dim3(15, KSLICES), 256>>>(x, W);
    k_simw<<<dim3(BB, 8), 128>>>(mem, bias);
    k_alloc<<<BB, 1024>>>(bias, usage, wwold, rw, link);
    k_linkmv<<<dim3(BB, NSTRIPS+8), 256>>>(link, rw, mem);
    k_read<<<dim3(BB,RR), 512>>>(prec, rw, out);
}